// round 11
// baseline (speedup 1.0000x reference)
#include <cuda_runtime.h>
#include <cstdint>

#define B_     8
#define S_     2048
#define N_     4096
#define D_     256
#define SLOTS  (D_ / 4)      // 64 float4 per row
#define BLK    16            // block >= max span extent (width <= 15 -> <= 16 rows)
#define NBLK   (S_ / BLK)    // 128

// Scratch (fp32): block-local inclusive prefix P (16.8 MB) + block totals T (1 MB).
// Span sum over rows [low, end]:
//   sum = P[end] + (cross ? T[blkE-1] : 0) - (haveSub ? P[low-1] : 0)
// cross = blk(low) != blk(end); cross => haveSub (width <= 15).
__device__ float g_P[(size_t)B_ * S_ * D_];            // 16.8 MB
__device__ float g_T[(size_t)B_ * NBLK * D_];          // 1 MB (hot in L2/L1)

// ── K1: streaming block-local prefix + total (R10 measured ~3.5 us) ──────────
// thread = (b, blk, slot); 65536 threads, 512 CTAs of 128.
__global__ __launch_bounds__(128) void k_prep(const float4* __restrict__ seq4)
{
    const int tid  = blockIdx.x * 128 + threadIdx.x;
    const int slot = tid & (SLOTS - 1);
    const int p    = tid >> 6;                  // (b, blk)
    const int blk  = p & (NBLK - 1);
    const int b    = p >> 7;                    // NBLK = 128

    const size_t base = ((size_t)b * S_ + (size_t)blk * BLK) * SLOTS + slot;
    const float4* __restrict__ q  = seq4 + base;
    float4* __restrict__        Pp = reinterpret_cast<float4*>(g_P) + base;

    float4 s = make_float4(0.f, 0.f, 0.f, 0.f);
#pragma unroll
    for (int r = 0; r < BLK; ++r) {
        const float4 v = __ldg(q + r * SLOTS);
        s.x += v.x; s.y += v.y; s.z += v.z; s.w += v.w;
        Pp[r * SLOTS] = s;                       // streaming store
    }
    reinterpret_cast<float4*>(g_T)[((size_t)b * NBLK + blk) * SLOTS + slot] = s;
}

// ── K2: spans — warp per span, 2x float4/thread (R9 measured 11.1 us) ────────
// blockDim 256 -> 8 spans per block, grid = 4096.
__global__ __launch_bounds__(256) void k_spans(
    const int2* __restrict__ spans,     // [B, N]
    float4*     __restrict__ out4)      // [B, N, D/4]
{
    const int span = blockIdx.x * 8 + (threadIdx.x >> 5);
    const int lane = threadIdx.x & 31;
    const int b    = span >> 12;                 // N_ = 4096

    const int2 se  = __ldg(&spans[span]);
    const int end  = se.y;
    const int m    = min(end - se.x, end);       // mask(w) <=> w <= m
    const int low  = end - m;                    // rows [low, end], count m+1

    const bool haveSub = (low & (BLK - 1)) != 0;
    const bool cross   = (low >> 4) != (end >> 4);   // => haveSub, blkE >= 1
    const int  selRow  = max(low - 1, 0);

    const float4* __restrict__ P4 = reinterpret_cast<const float4*>(g_P)
                                  + (size_t)b * S_ * SLOTS;
    const float4* __restrict__ hiP = P4 + (size_t)end    * SLOTS + lane;
    const float4* __restrict__ sbP = P4 + (size_t)selRow * SLOTS + lane;

    // Four unconditional loads (deep MLP).
    const float4 hi0 = __ldg(hiP);
    const float4 hi1 = __ldg(hiP + 32);
    const float4 sb0 = __ldg(sbP);
    const float4 sb1 = __ldg(sbP + 32);

    const float inv = 1.0f / fmaxf((float)(m + 1), 1e-13f);
    const float fs  = haveSub ? inv : 0.0f;

    float4 r0, r1;
    r0.x = hi0.x * inv - sb0.x * fs;  r0.y = hi0.y * inv - sb0.y * fs;
    r0.z = hi0.z * inv - sb0.z * fs;  r0.w = hi0.w * inv - sb0.w * fs;
    r1.x = hi1.x * inv - sb1.x * fs;  r1.y = hi1.y * inv - sb1.y * fs;
    r1.z = hi1.z * inv - sb1.z * fs;  r1.w = hi1.w * inv - sb1.w * fs;

    if (cross) {   // warp-uniform; ~47% of spans. T hot in L1/L2 (1 MB).
        const float4* __restrict__ tP = reinterpret_cast<const float4*>(g_T)
            + ((size_t)b * NBLK + ((end >> 4) - 1)) * SLOTS + lane;
        const float4 t0 = __ldg(tP);
        const float4 t1 = __ldg(tP + 32);
        r0.x += t0.x * inv;  r0.y += t0.y * inv;
        r0.z += t0.z * inv;  r0.w += t0.w * inv;
        r1.x += t1.x * inv;  r1.y += t1.y * inv;
        r1.z += t1.z * inv;  r1.w += t1.w * inv;
    }

    float4* __restrict__ o = out4 + (size_t)span * SLOTS + lane;
    o[0]  = r0;
    o[32] = r1;
}

extern "C" void kernel_launch(void* const* d_in, const int* in_sizes, int n_in,
                              void* d_out, int out_size)
{
    const float4* seq4  = (const float4*)d_in[0];  // sequence_tensor [B,S,D] f32
    const int2*   spans = (const int2*)  d_in[1];  // span_indices    [B,N,2] i32
    float4*       out4  = (float4*)d_out;          // [B,N,D] f32

    k_prep <<<(B_ * NBLK * SLOTS) / 128, 128>>>(seq4);
    k_spans<<<(B_ * N_) / 8, 256>>>(spans, out4);
}